// round 3
// baseline (speedup 1.0000x reference)
#include <cuda_runtime.h>

#define SQ 256
#define BQ 256
#define DQ 256
#define HQ 8
#define STR (BQ * 32)   // floats per timestep in d_pre

// scratch: pre-activations, padded by 4 steps for branch-free prefetch
__device__ float d_pre[(SQ + 4) * STR];

__device__ __forceinline__ float htanh(float x) {
    float r;
    asm("tanh.approx.f32 %0, %1;" : "=f"(r) : "f"(x));
    return r;
}

// ---------------------------------------------------------------------------
// Kernel 1: pre[t,b,o] = x[t,b,:] @ Wx[o,:] + bias[o] + theta[o]
// ---------------------------------------------------------------------------
__global__ __launch_bounds__(256) void qlstm_gemm(
    const float* __restrict__ x,
    const float* __restrict__ Wf, const float* __restrict__ bf,
    const float* __restrict__ Wi, const float* __restrict__ bi,
    const float* __restrict__ Wu, const float* __restrict__ bu,
    const float* __restrict__ Wo, const float* __restrict__ bo,
    const float* __restrict__ thf, const float* __restrict__ thi,
    const float* __restrict__ thu, const float* __restrict__ tho)
{
    __shared__ float sW[32][260];
    __shared__ float sBias[32];

    int tid = threadIdx.x;

    #pragma unroll 4
    for (int idx = tid; idx < 32 * 256; idx += 256) {
        int o = idx >> 8;
        int d = idx & 255;
        int g = o >> 3, kk = o & 7;
        const float* Wg = (g == 0) ? Wf : (g == 1) ? Wi : (g == 2) ? Wu : Wo;
        sW[o][d] = Wg[kk * 264 + d];
    }
    if (tid < 32) {
        int g = tid >> 3, kk = tid & 7;
        const float* bg = (g == 0) ? bf : (g == 1) ? bi : (g == 2) ? bu : bo;
        const float* tg = (g == 0) ? thf : (g == 1) ? thi : (g == 2) ? thu : tho;
        sBias[tid] = bg[kk] + tg[kk];
    }
    __syncthreads();

    int warp = tid >> 5, lane = tid & 31;
    int o1 = lane & 15, o2 = o1 + 16;
    int rb = blockIdx.x * 128 + warp * 16 + (lane >> 4) * 8;

    float acc0[8], acc1[8];
    #pragma unroll
    for (int r = 0; r < 8; r++) { acc0[r] = 0.f; acc1[r] = 0.f; }

    const float* xp = x + (size_t)rb * 256;

    #pragma unroll 4
    for (int d = 0; d < 256; d += 4) {
        float4 w1 = *reinterpret_cast<const float4*>(&sW[o1][d]);
        float4 w2 = *reinterpret_cast<const float4*>(&sW[o2][d]);
        #pragma unroll
        for (int r = 0; r < 8; r++) {
            float4 xv = *reinterpret_cast<const float4*>(xp + r * 256 + d);
            acc0[r] = fmaf(xv.x, w1.x, acc0[r]);
            acc0[r] = fmaf(xv.y, w1.y, acc0[r]);
            acc0[r] = fmaf(xv.z, w1.z, acc0[r]);
            acc0[r] = fmaf(xv.w, w1.w, acc0[r]);
            acc1[r] = fmaf(xv.x, w2.x, acc1[r]);
            acc1[r] = fmaf(xv.y, w2.y, acc1[r]);
            acc1[r] = fmaf(xv.z, w2.z, acc1[r]);
            acc1[r] = fmaf(xv.w, w2.w, acc1[r]);
        }
    }

    float bb1 = sBias[o1], bb2 = sBias[o2];
    #pragma unroll
    for (int r = 0; r < 8; r++) {
        d_pre[(size_t)(rb + r) * 32 + o1] = acc0[r] + bb1;
        d_pre[(size_t)(rb + r) * 32 + o2] = acc1[r] + bb2;
    }
}

// ---------------------------------------------------------------------------
// Kernel 2: sequential LSTM, one warp per batch row. lane = g*8+k.
// Exchange via per-warp smem (h, cos) + 4 SHFLs (gate quad gather).
// ---------------------------------------------------------------------------
__global__ __launch_bounds__(64) void qlstm_recur(
    const float* __restrict__ Wf, const float* __restrict__ Wi,
    const float* __restrict__ Wu, const float* __restrict__ Wo,
    const float* __restrict__ hx, const float* __restrict__ cx,
    float* __restrict__ out)
{
    __shared__ float smh[2][8];
    __shared__ float smc[2][32];

    int warp = threadIdx.x >> 5;
    int lane = threadIdx.x & 31;
    int w = (blockIdx.x << 1) | warp;
    int g = lane >> 3, k = lane & 7;

    float* Hb = smh[warp];
    float* Cb = smc[warp];

    const float* Wg = (g == 0) ? Wf : (g == 1) ? Wi : (g == 2) ? Wu : Wo;
    float wh0 = Wg[k * 264 + 256 + 0], wh1 = Wg[k * 264 + 256 + 1];
    float wh2 = Wg[k * 264 + 256 + 2], wh3 = Wg[k * 264 + 256 + 3];
    float wh4 = Wg[k * 264 + 256 + 4], wh5 = Wg[k * 264 + 256 + 5];
    float wh6 = Wg[k * 264 + 256 + 6], wh7 = Wg[k * 264 + 256 + 7];

    // per-lane activation constants: sigmoid = 0.5 + 0.5*tanh(x/2); u-gate = tanh(x)
    float Mc = (g == 2) ? 1.0f : 0.5f;
    float Ac = (g == 2) ? 1.0f : 0.5f;
    float Bc = (g == 2) ? 0.0f : 0.5f;

    float h = hx[w * 8 + k];
    float c = cx[w * 8 + k];
    Hb[k] = h;                       // 4-way same-value write, benign
    __syncwarp();

    // prefetch pipeline, distance 4
    const float* pb = d_pre + w * 32 + lane;
    float q0 = pb[0 * STR], q1 = pb[1 * STR], q2 = pb[2 * STR], q3 = pb[3 * STR];
    const float* pf = pb + 4 * STR;

    float* op = out + (size_t)w * HQ + k;
    const unsigned FULL = 0xffffffffu;

    bool m1p = (k >= 1), m2p = (k >= 2), m3p = (k >= 3), m4p = (k >= 4),
         m5p = (k >= 5), m6p = (k >= 6), m7p = (k >= 7);

#define QSTEP(PQ)                                                            \
    {                                                                        \
        float4 hv0 = *reinterpret_cast<const float4*>(Hb);                   \
        float4 hv1 = *reinterpret_cast<const float4*>(Hb + 4);               \
        float a0 = fmaf(wh0, hv0.x, (PQ));                                   \
        float a1 = wh1 * hv0.y;                                              \
        a0 = fmaf(wh2, hv0.z, a0);                                           \
        a1 = fmaf(wh3, hv0.w, a1);                                           \
        a0 = fmaf(wh4, hv1.x, a0);                                           \
        a1 = fmaf(wh5, hv1.y, a1);                                           \
        a0 = fmaf(wh6, hv1.z, a0);                                           \
        a1 = fmaf(wh7, hv1.w, a1);                                           \
        float cv = __cosf(a0 + a1);                                          \
        Cb[lane] = cv;                                                       \
        __syncwarp();                                                        \
        float4 cA = *reinterpret_cast<const float4*>(Cb + g * 8);            \
        float4 cB = *reinterpret_cast<const float4*>(Cb + g * 8 + 4);        \
        float t0 = cA.x * Mc;                                                \
        float m1 = m1p ? cA.y : 1.f;                                         \
        float m2 = m2p ? cA.z : 1.f;                                         \
        float m3 = m3p ? cA.w : 1.f;                                         \
        float m4 = m4p ? cB.x : 1.f;                                         \
        float m5 = m5p ? cB.y : 1.f;                                         \
        float m6 = m6p ? cB.z : 1.f;                                         \
        float m7 = m7p ? cB.w : 1.f;                                         \
        float p = ((t0 * m1) * (m2 * m3)) * ((m4 * m5) * (m6 * m7));         \
        float act = fmaf(Ac, htanh(p), Bc);                                  \
        float fv = __shfl_sync(FULL, act, k);                                \
        float iv = __shfl_sync(FULL, act, 8 + k);                            \
        float uv = __shfl_sync(FULL, act, 16 + k);                           \
        float ov = __shfl_sync(FULL, act, 24 + k);                           \
        c = fmaf(fv, c, iv * uv);                                            \
        h = ov * htanh(c);                                                   \
        Hb[k] = h;                                                           \
        *op = h;                                                             \
        op += BQ * HQ;                                                       \
        __syncwarp();                                                        \
    }

    for (int t = 0; t < SQ; t += 2) {
        QSTEP(q0); q0 = q2; q2 = pf[0]; pf += STR;
        QSTEP(q1); q1 = q3; q3 = pf[0]; pf += STR;
    }
#undef QSTEP

    // hT, cT (replicated across gate groups -> benign same-value stores)
    out[(size_t)SQ * BQ * HQ + (size_t)w * HQ + k] = h;
    out[(size_t)SQ * BQ * HQ + (size_t)BQ * HQ + (size_t)w * HQ + k] = c;
}

extern "C" void kernel_launch(void* const* d_in, const int* in_sizes, int n_in,
                              void* d_out, int out_size)
{
    const float* x   = (const float*)d_in[0];
    const float* hx  = (const float*)d_in[1];
    const float* cx  = (const float*)d_in[2];
    const float* Wf  = (const float*)d_in[3];
    const float* bf  = (const float*)d_in[4];
    const float* Wi  = (const float*)d_in[5];
    const float* bi  = (const float*)d_in[6];
    const float* Wu  = (const float*)d_in[7];
    const float* bu  = (const float*)d_in[8];
    const float* Wo  = (const float*)d_in[9];
    const float* bo  = (const float*)d_in[10];
    const float* tf  = (const float*)d_in[11];
    const float* ti  = (const float*)d_in[12];
    const float* tu  = (const float*)d_in[13];
    const float* to_ = (const float*)d_in[14];

    qlstm_gemm<<<512, 256>>>(x, Wf, bf, Wi, bi, Wu, bu, Wo, bo, tf, ti, tu, to_);
    qlstm_recur<<<128, 64>>>(Wf, Wi, Wu, Wo, hx, cx, (float*)d_out);
}